// round 9
// baseline (speedup 1.0000x reference)
#include <cuda_runtime.h>
#include <cooperative_groups.h>

namespace cg = cooperative_groups;

// Problem constants (fixed shapes)
#define NN    5000      // graph nodes
#define MM    10        // template nodes
#define SR    11        // smem row stride (gcd(11,32)=1 -> conflict-free)
#define NT    16        // templates
#define FF    128       // features
#define NFW   3         // Frank-Wolfe iters
#define NSINK 10        // Sinkhorn iters
#define NC    8         // CTAs per cluster (per template)
#define RPC   (NN/NC)   // rows per CTA = 625
#define TPB   512
#define NWARP (TPB/32)
#define WS    160       // bitmap words per row (157 used, padded)
#define EMAX  80000

// ---------------- device scratch (static; no allocation) ----------------
__device__ unsigned int g_bitmap[NN * WS];       // zero-init; k_fill leaves it clean
__device__ int   g_rowptr[NN + 1];
__device__ int   g_cols[EMAX];
__device__ float g_Y[(size_t)NT * NN * MM];      // dT@C2 per template

// ---------------- preprocessing kernels ----------------
__global__ void k_mark(const int* __restrict__ ei, int E) {
    int e = blockIdx.x * blockDim.x + threadIdx.x;
    if (e >= E) return;
    int s = ei[e];
    int d = ei[E + e];
    atomicOr(&g_bitmap[s * WS + (d >> 5)], 1u << (d & 31));
}

// Fused degree + exclusive scan, single block of 1024 threads.
// Phase A: warp-per-row popcount into smem. Phase B: shuffle scan -> g_rowptr.
__global__ void k_degscan() {
    __shared__ int sdeg[NN];
    __shared__ int wsum[32];
    int tid = threadIdx.x, lane = tid & 31, w = tid >> 5;

    // A: deduped degree per row
    for (int r = w; r < NN; r += 32) {
        const unsigned int* bp = g_bitmap + (size_t)r * WS;
        int c = 0;
        #pragma unroll
        for (int k = 0; k < 5; k++) c += __popc(bp[lane + 32 * k]);
        #pragma unroll
        for (int o = 16; o; o >>= 1) c += __shfl_xor_sync(0xffffffffu, c, o);
        if (lane == 0) sdeg[r] = c;
    }
    __syncthreads();

    // B: exclusive scan of sdeg -> g_rowptr (5 elems/thread + 2-level shuffle scan)
    int base = tid * 5, loc[5], s = 0;
    #pragma unroll
    for (int k = 0; k < 5; k++) {
        int v = (base + k < NN) ? sdeg[base + k] : 0;
        loc[k] = v; s += v;
    }
    int inc = s;
    #pragma unroll
    for (int o = 1; o < 32; o <<= 1) {
        int v = __shfl_up_sync(0xffffffffu, inc, o);
        if (lane >= o) inc += v;
    }
    if (lane == 31) wsum[w] = inc;
    __syncthreads();
    if (w == 0) {
        int v2 = wsum[lane], i2 = v2;
        #pragma unroll
        for (int o = 1; o < 32; o <<= 1) {
            int t = __shfl_up_sync(0xffffffffu, i2, o);
            if (lane >= o) i2 += t;
        }
        wsum[lane] = i2 - v2;   // exclusive warp offsets
    }
    __syncthreads();
    int excl = wsum[w] + inc - s;
    #pragma unroll
    for (int k = 0; k < 5; k++) {
        if (base + k < NN) { g_rowptr[base + k] = excl; excl += loc[k]; }
    }
    if (tid == 1023) g_rowptr[NN] = excl;
}

// one warp per row: emit sorted column indices (deterministic CSR) AND clear bitmap
__global__ void k_fill() {
    int w    = (blockIdx.x * blockDim.x + threadIdx.x) >> 5;
    int lane = threadIdx.x & 31;
    if (w >= NN) return;
    unsigned int* bp = g_bitmap + (size_t)w * WS;
    unsigned int wd[5];
    int c = 0;
    #pragma unroll
    for (int k = 0; k < 5; k++) {
        wd[k] = bp[lane * 5 + k];
        bp[lane * 5 + k] = 0u;
        c += __popc(wd[k]);
    }
    int inc = c;
    #pragma unroll
    for (int o = 1; o < 32; o <<= 1) {
        int v = __shfl_up_sync(0xffffffffu, inc, o);
        if (lane >= o) inc += v;
    }
    int pos = g_rowptr[w] + inc - c;
    #pragma unroll
    for (int k = 0; k < 5; k++) {
        unsigned int x = wd[k];
        int bb = (lane * 5 + k) * 32;
        while (x) {
            int b = __ffs(x) - 1;
            g_cols[pos++] = bb + b;
            x &= x - 1;
        }
    }
}

// ---------------- main FGW kernel: one 8-CTA cluster per template ----------------
struct __align__(16) Smem {
    float M[RPC * SR];
    float K[RPC * SR];      // holds G, then K = exp(-(G-c)/reg)
    float T[RPC * SR];
    float ATC[RPC * SR];
    float AdT[RPC * SR];
    float DegN[RPC];        // deg_i / N
    float U[RPC];
    float F2[MM * FF];
    float C2[MM * MM];
    float q[MM], qC2[MM], cc[MM], fsq[MM];
    float V[MM];
    float Pub[2][16];       // double-buffered cluster exchange
    float Wred[NWARP][16];  // block-reduction scratch
    float Scal[4];          // [0]=reg [1]=cmin [2]=gamma
};

__global__ void __launch_bounds__(TPB, 1) __cluster_dims__(NC, 1, 1)
k_main(const float* __restrict__ x,
       const float* __restrict__ tA,
       const float* __restrict__ tF,
       const float* __restrict__ q0,
       const float* __restrict__ a0,
       float* __restrict__ out)
{
    extern __shared__ char smem_raw[];
    Smem* s = reinterpret_cast<Smem*>(smem_raw);
    cg::cluster_group cluster = cg::this_cluster();
    const int rank = (int)cluster.block_rank();
    const int tpl  = blockIdx.x / NC;
    const int tid  = threadIdx.x;
    const int wid  = tid >> 5, lane = tid & 31;
    const int r0   = rank * RPC;
    const float P  = 1.0f / (float)NN;
    const float alpha = 1.0f / (1.0f + expf(-a0[0]));
    const float oma = 1.0f - alpha, ta = 2.0f * alpha;
    int par = 0;

    // ---- phase 0: per-template small data ----
    for (int i = tid; i < MM * FF; i += TPB) s->F2[i] = tF[(size_t)tpl * MM * FF + i];
    if (tid < MM * MM) s->C2[tid] = tA[tpl * MM * MM + tid];
    if (tid == 0) {
        float qq[MM]; float mx = -1e30f;
        #pragma unroll
        for (int k = 0; k < MM; k++) { qq[k] = q0[tpl * MM + k]; mx = fmaxf(mx, qq[k]); }
        float ssum = 0.f;
        #pragma unroll
        for (int k = 0; k < MM; k++) { qq[k] = expf(qq[k] - mx); ssum += qq[k]; }
        #pragma unroll
        for (int k = 0; k < MM; k++) s->q[k] = qq[k] / ssum;
    }
    __syncthreads();
    if (tid < MM) {
        int j = tid;
        float a1 = 0.f, a2 = 0.f, a3 = 0.f;
        #pragma unroll
        for (int k = 0; k < MM; k++) {
            a1 += s->q[k] * s->C2[k * MM + j];
            float cj = s->C2[j * MM + k];
            a2 += cj * cj * s->q[k];
        }
        for (int c = 0; c < FF; c++) { float fv = s->F2[j * FF + c]; a3 += fv * fv; }
        s->qC2[j] = a1; s->cc[j] = a2; s->fsq[j] = a3;
    }
    __syncthreads();

    // ---- phase 1: M (feature cost), DegN, T0 = p q^T, ATC0 (closed form) ----
    for (int r = wid; r < RPC; r += NWARP) {
        int gi = r0 + r;
        const float* xr = x + (size_t)gi * FF;
        float acc[MM];
        #pragma unroll
        for (int j = 0; j < MM; j++) acc[j] = 0.f;
        float xs = 0.f;
        #pragma unroll
        for (int c = 0; c < FF / 32; c++) {
            float xv = xr[c * 32 + lane];
            xs += xv * xv;
            #pragma unroll
            for (int j = 0; j < MM; j++) acc[j] += xv * s->F2[j * FF + c * 32 + lane];
        }
        #pragma unroll
        for (int o = 16; o; o >>= 1) {
            xs += __shfl_xor_sync(0xffffffffu, xs, o);
            #pragma unroll
            for (int j = 0; j < MM; j++) acc[j] += __shfl_xor_sync(0xffffffffu, acc[j], o);
        }
        float dn = (float)(g_rowptr[gi + 1] - g_rowptr[gi]) * P;
        if (lane == 0) s->DegN[r] = dn;
        if (lane < MM) {
            int j = lane;
            s->M[r * SR + j]   = xs + s->fsq[j] - 2.f * acc[j];
            s->T[r * SR + j]   = P * s->q[j];
            s->ATC[r * SR + j] = dn * s->qC2[j];
        }
    }
    __syncthreads();

    // ---- Frank-Wolfe loop ----
    for (int fw = 0; fw < NFW; fw++) {
        // (a) G = (1-a)M + 2a(constC - 2 ATC); stats: sum|G|, min G
        float psum = 0.f, pmin = 1e30f;
        for (int li = tid; li < RPC; li += TPB) {
            float dn = s->DegN[li];
            #pragma unroll
            for (int j = 0; j < MM; j++) {
                int e = li * SR + j;
                float g = oma * s->M[e] + ta * (dn + s->cc[j] - 2.f * s->ATC[e]);
                s->K[e] = g;
                psum += fabsf(g);
                pmin = fminf(pmin, g);
            }
        }
        #pragma unroll
        for (int o = 16; o; o >>= 1) {
            psum += __shfl_xor_sync(0xffffffffu, psum, o);
            pmin = fminf(pmin, __shfl_xor_sync(0xffffffffu, pmin, o));
        }
        if (lane == 0) { s->Wred[wid][0] = psum; s->Wred[wid][1] = pmin; }
        __syncthreads();
        if (tid == 0) {
            float bs = 0.f, bm = 1e30f;
            for (int w = 0; w < NWARP; w++) { bs += s->Wred[w][0]; bm = fminf(bm, s->Wred[w][1]); }
            s->Pub[par][0] = bs; s->Pub[par][1] = bm;
        }
        cluster.sync();
        if (tid == 0) {
            float bs = 0.f, bm = 1e30f;
            for (int r = 0; r < NC; r++) {
                const float* rp = cluster.map_shared_rank(&s->Pub[0][0], r);
                bs += rp[par * 16 + 0];
                bm = fminf(bm, rp[par * 16 + 1]);
            }
            s->Scal[0] = 0.05f * (bs / (float)(NN * MM)) + 1e-9f;  // reg
            s->Scal[1] = bm;                                        // cmin
        }
        if (tid < MM) s->V[tid] = 1.f;   // reset Sinkhorn scaling (g=0)
        par ^= 1;
        __syncthreads();

        // (b) K = exp(-(G - cmin)/reg)  (exact shift invariance)
        {
            float reg = s->Scal[0], cmin = s->Scal[1];
            float inv = 1.0f / reg;
            for (int li = tid; li < RPC; li += TPB) {
                #pragma unroll
                for (int j = 0; j < MM; j++) {
                    int e = li * SR + j;
                    s->K[e] = expf(fmaxf((cmin - s->K[e]) * inv, -80.f));
                }
            }
        }

        // (c) Sinkhorn: u = p/(Kv); v = q/(K^T u); one cluster.sync per iter
        for (int it = 0; it < NSINK; it++) {
            float vr[MM];
            #pragma unroll
            for (int j = 0; j < MM; j++) vr[j] = s->V[j];
            float col[MM];
            #pragma unroll
            for (int j = 0; j < MM; j++) col[j] = 0.f;
            for (int li = tid; li < RPC; li += TPB) {
                float kr[MM];
                #pragma unroll
                for (int j = 0; j < MM; j++) kr[j] = s->K[li * SR + j];
                float kv = 0.f;
                #pragma unroll
                for (int j = 0; j < MM; j++) kv += kr[j] * vr[j];
                float u = P / kv;
                s->U[li] = u;
                #pragma unroll
                for (int j = 0; j < MM; j++) col[j] += kr[j] * u;
            }
            #pragma unroll
            for (int o = 16; o; o >>= 1) {
                #pragma unroll
                for (int j = 0; j < MM; j++) col[j] += __shfl_xor_sync(0xffffffffu, col[j], o);
            }
            if (lane == 0) {
                #pragma unroll
                for (int j = 0; j < MM; j++) s->Wred[wid][j] = col[j];
            }
            __syncthreads();
            if (tid < MM) {
                float t = 0.f;
                for (int w = 0; w < NWARP; w++) t += s->Wred[w][tid];
                s->Pub[par][tid] = t;
            }
            cluster.sync();
            if (tid < MM) {
                float tot = 0.f;
                for (int r = 0; r < NC; r++) {
                    const float* rp = cluster.map_shared_rank(&s->Pub[0][0], r);
                    tot += rp[par * 16 + tid];
                }
                s->V[tid] = s->q[tid] / tot;
            }
            par ^= 1;
            __syncthreads();
        }

        // (d) dT = u.K.v - T; Y = dT@C2 -> global; partial dots for b
        float pM = 0.f, pC = 0.f, pA = 0.f;
        {
            float vr[MM];
            #pragma unroll
            for (int j = 0; j < MM; j++) vr[j] = s->V[j];
            for (int li = tid; li < RPC; li += TPB) {
                float u = s->U[li];
                float d[MM];
                #pragma unroll
                for (int j = 0; j < MM; j++) {
                    int e = li * SR + j;
                    d[j] = u * s->K[e] * vr[j] - s->T[e];
                }
                float dn = s->DegN[li];
                #pragma unroll
                for (int j = 0; j < MM; j++) {
                    int e = li * SR + j;
                    pM += s->M[e] * d[j];
                    pC += (dn + s->cc[j]) * d[j];
                    pA += s->ATC[e] * d[j];
                }
                float* yp = g_Y + ((size_t)tpl * NN + (r0 + li)) * MM;
                #pragma unroll
                for (int jj = 0; jj < MM; jj++) {
                    float y = 0.f;
                    #pragma unroll
                    for (int j = 0; j < MM; j++) y += d[j] * s->C2[j * MM + jj];
                    yp[jj] = y;
                }
            }
        }
        __threadfence();
        cluster.sync();

        // (e) SpMM: AdTC = A @ Y (CSR, deduped, sorted -> deterministic); pa
        float pa = 0.f;
        {
            float vr[MM];
            #pragma unroll
            for (int j = 0; j < MM; j++) vr[j] = s->V[j];
            for (int li = tid; li < RPC; li += TPB) {
                int gi = r0 + li;
                int b = g_rowptr[gi], en = g_rowptr[gi + 1];
                float acc[MM];
                #pragma unroll
                for (int j = 0; j < MM; j++) acc[j] = 0.f;
                for (int p2 = b; p2 < en; p2++) {
                    int col = g_cols[p2];
                    const float2* yp = reinterpret_cast<const float2*>(
                        g_Y + ((size_t)tpl * NN + col) * MM);
                    float2 v0 = __ldg(yp + 0), v1 = __ldg(yp + 1), v2 = __ldg(yp + 2),
                           v3 = __ldg(yp + 3), v4 = __ldg(yp + 4);
                    acc[0] += v0.x; acc[1] += v0.y;
                    acc[2] += v1.x; acc[3] += v1.y;
                    acc[4] += v2.x; acc[5] += v2.y;
                    acc[6] += v3.x; acc[7] += v3.y;
                    acc[8] += v4.x; acc[9] += v4.y;
                }
                float u = s->U[li];
                #pragma unroll
                for (int j = 0; j < MM; j++) {
                    int e = li * SR + j;
                    s->AdT[e] = acc[j];
                    float d = u * s->K[e] * vr[j] - s->T[e];
                    pa += acc[j] * d;
                }
            }
        }

        // (f) reduce (pa, pM, pC, pA) block+cluster; compute gamma
        #pragma unroll
        for (int o = 16; o; o >>= 1) {
            pa += __shfl_xor_sync(0xffffffffu, pa, o);
            pM += __shfl_xor_sync(0xffffffffu, pM, o);
            pC += __shfl_xor_sync(0xffffffffu, pC, o);
            pA += __shfl_xor_sync(0xffffffffu, pA, o);
        }
        if (lane == 0) {
            s->Wred[wid][0] = pa; s->Wred[wid][1] = pM;
            s->Wred[wid][2] = pC; s->Wred[wid][3] = pA;
        }
        __syncthreads();
        if (tid == 0) {
            float t0 = 0, t1 = 0, t2 = 0, t3 = 0;
            for (int w = 0; w < NWARP; w++) {
                t0 += s->Wred[w][0]; t1 += s->Wred[w][1];
                t2 += s->Wred[w][2]; t3 += s->Wred[w][3];
            }
            s->Pub[par][0] = t0; s->Pub[par][1] = t1;
            s->Pub[par][2] = t2; s->Pub[par][3] = t3;
        }
        cluster.sync();
        if (tid == 0) {
            float Ta = 0, Tm = 0, Tc = 0, TA = 0;
            for (int r = 0; r < NC; r++) {
                const float* rp = cluster.map_shared_rank(&s->Pub[0][0], r);
                Ta += rp[par * 16 + 0]; Tm += rp[par * 16 + 1];
                Tc += rp[par * 16 + 2]; TA += rp[par * 16 + 3];
            }
            float a = -2.f * alpha * Ta;
            float b = oma * Tm + alpha * (Tc - 4.f * TA);
            float gam;
            if (a > 0.f) {
                gam = -b / (2.f * a + 1e-16f);
                gam = fminf(fmaxf(gam, 0.f), 1.f);
            } else {
                gam = (a + b < 0.f) ? 1.f : 0.f;
            }
            s->Scal[2] = gam;
        }
        par ^= 1;
        __syncthreads();

        // (g) T += gam*dT; ATC += gam*AdTC
        {
            float gam = s->Scal[2];
            float vr[MM];
            #pragma unroll
            for (int j = 0; j < MM; j++) vr[j] = s->V[j];
            for (int li = tid; li < RPC; li += TPB) {
                float u = s->U[li];
                #pragma unroll
                for (int j = 0; j < MM; j++) {
                    int e = li * SR + j;
                    float d = u * s->K[e] * vr[j] - s->T[e];
                    s->T[e]   += gam * d;
                    s->ATC[e] += gam * s->AdT[e];
                }
            }
        }
        __syncthreads();
    }

    // ---- final FGW distance ----
    float pd = 0.f;
    for (int li = tid; li < RPC; li += TPB) {
        float dn = s->DegN[li];
        #pragma unroll
        for (int j = 0; j < MM; j++) {
            int e = li * SR + j;
            float t = s->T[e];
            pd += oma * s->M[e] * t + alpha * ((dn + s->cc[j]) * t - 2.f * s->ATC[e] * t);
        }
    }
    #pragma unroll
    for (int o = 16; o; o >>= 1) pd += __shfl_xor_sync(0xffffffffu, pd, o);
    if (lane == 0) s->Wred[wid][0] = pd;
    __syncthreads();
    if (tid == 0) {
        float bs = 0.f;
        for (int w = 0; w < NWARP; w++) bs += s->Wred[w][0];
        s->Pub[par][0] = bs;
    }
    cluster.sync();
    if (rank == 0 && tid == 0) {
        float tot = 0.f;
        for (int r = 0; r < NC; r++) {
            const float* rp = cluster.map_shared_rank(&s->Pub[0][0], r);
            tot += rp[par * 16 + 0];
        }
        out[tpl] = tot;
    }
    cluster.sync();  // keep all CTAs alive until DSMEM reads complete
}

// ---------------- launch ----------------
extern "C" void kernel_launch(void* const* d_in, const int* in_sizes, int n_in,
                              void* d_out, int out_size)
{
    const float* x  = (const float*)d_in[0];
    const int*   ei = (const int*)  d_in[1];
    const float* tA = (const float*)d_in[2];
    const float* tF = (const float*)d_in[3];
    const float* q0 = (const float*)d_in[4];
    const float* a0 = (const float*)d_in[5];
    float* out = (float*)d_out;
    int E = in_sizes[1] / 2;

    cudaFuncSetAttribute(k_main, cudaFuncAttributeMaxDynamicSharedMemorySize,
                         (int)sizeof(Smem));

    k_mark<<<(E + 255) / 256, 256>>>(ei, E);          // launch 1
    k_degscan<<<1, 1024>>>();                          // launch 2
    k_fill<<<(NN * 32 + 255) / 256, 256>>>();          // launch 3
    k_main<<<NT * NC, TPB, sizeof(Smem)>>>(x, tA, tF, q0, a0, out);  // launch 4 -> profiled
}

// round 10
// speedup vs baseline: 1.1422x; 1.1422x over previous
#include <cuda_runtime.h>
#include <cooperative_groups.h>

namespace cg = cooperative_groups;

// Problem constants (fixed shapes)
#define NN    5000      // graph nodes
#define MM    10        // template nodes
#define SR    11        // smem row stride for row-major arrays (gcd(11,32)=1)
#define KSTR  640       // KT column-major stride (pad 625 -> 640, float4-able)
#define NT    16        // templates
#define FF    128       // features
#define NFW   3         // Frank-Wolfe iters
#define NSINK 10        // Sinkhorn iters
#define NC    8         // CTAs per cluster (per template)
#define RPC   (NN/NC)   // rows per CTA = 625
#define TPB   512
#define NWARP (TPB/32)
#define WS    160       // bitmap words per row (157 used, padded)
#define EMAX  80000

// ---------------- device scratch (static; no allocation) ----------------
__device__ unsigned int g_bitmap[NN * WS];       // zero-init; k_fill leaves it clean
__device__ int   g_deg[NN];
__device__ int   g_rowptr[NN + 1];
__device__ int   g_cols[EMAX];
__device__ int   g_ctr;                          // k_degscan last-block counter (self-resetting)
__device__ float g_Y[(size_t)NT * NN * MM];      // dT@C2 per template

// ---------------- preprocessing kernels ----------------
__global__ void k_mark(const int* __restrict__ ei, int E) {
    int e = blockIdx.x * blockDim.x + threadIdx.x;
    if (e >= E) return;
    int s = ei[e];
    int d = ei[E + e];
    atomicOr(&g_bitmap[s * WS + (d >> 5)], 1u << (d & 31));
}

// Grid-wide dedup degree (warp-per-row) + last-block exclusive scan -> g_rowptr.
__global__ void k_degscan() {
    __shared__ int isLast;
    __shared__ int wsum[16];
    int gw   = (blockIdx.x * blockDim.x + threadIdx.x) >> 5;
    int lane = threadIdx.x & 31;
    if (gw < NN) {
        const unsigned int* bp = g_bitmap + (size_t)gw * WS;
        int c = 0;
        #pragma unroll
        for (int k = 0; k < 5; k++) c += __popc(bp[lane + 32 * k]);
        #pragma unroll
        for (int o = 16; o; o >>= 1) c += __shfl_xor_sync(0xffffffffu, c, o);
        if (lane == 0) g_deg[gw] = c;
    }
    __syncthreads();
    __threadfence();
    if (threadIdx.x == 0) isLast = (atomicAdd(&g_ctr, 1) == (int)gridDim.x - 1);
    __syncthreads();
    if (!isLast) return;

    // exclusive scan of g_deg[5000] with 512 threads, 10 elems each
    int tid = threadIdx.x, w = tid >> 5;
    int base = tid * 10, loc[10], ssum = 0;
    #pragma unroll
    for (int k = 0; k < 10; k++) {
        int v = (base + k < NN) ? g_deg[base + k] : 0;
        loc[k] = v; ssum += v;
    }
    int inc = ssum;
    #pragma unroll
    for (int o = 1; o < 32; o <<= 1) {
        int v = __shfl_up_sync(0xffffffffu, inc, o);
        if (lane >= o) inc += v;
    }
    if (lane == 31) wsum[w] = inc;
    __syncthreads();
    if (w == 0) {
        int v2 = (lane < 16) ? wsum[lane] : 0, i2 = v2;
        #pragma unroll
        for (int o = 1; o < 32; o <<= 1) {
            int t = __shfl_up_sync(0xffffffffu, i2, o);
            if (lane >= o) i2 += t;
        }
        if (lane < 16) wsum[lane] = i2 - v2;   // exclusive warp offsets
    }
    __syncthreads();
    int excl = wsum[w] + inc - ssum;
    #pragma unroll
    for (int k = 0; k < 10; k++) {
        if (base + k < NN) { g_rowptr[base + k] = excl; excl += loc[k]; }
    }
    if (tid == 511) g_rowptr[NN] = excl;   // all its loc are 0 -> excl = total
    if (tid == 0)   g_ctr = 0;             // reset for next call (determinism)
}

// one warp per row: emit sorted column indices (deterministic CSR) AND clear bitmap
__global__ void k_fill() {
    int w    = (blockIdx.x * blockDim.x + threadIdx.x) >> 5;
    int lane = threadIdx.x & 31;
    if (w >= NN) return;
    unsigned int* bp = g_bitmap + (size_t)w * WS;
    unsigned int wd[5];
    int c = 0;
    #pragma unroll
    for (int k = 0; k < 5; k++) {
        wd[k] = bp[lane * 5 + k];
        bp[lane * 5 + k] = 0u;
        c += __popc(wd[k]);
    }
    int inc = c;
    #pragma unroll
    for (int o = 1; o < 32; o <<= 1) {
        int v = __shfl_up_sync(0xffffffffu, inc, o);
        if (lane >= o) inc += v;
    }
    int pos = g_rowptr[w] + inc - c;
    #pragma unroll
    for (int k = 0; k < 5; k++) {
        unsigned int x = wd[k];
        int bb = (lane * 5 + k) * 32;
        while (x) {
            int b = __ffs(x) - 1;
            g_cols[pos++] = bb + b;
            x &= x - 1;
        }
    }
}

// ---------------- main FGW kernel: one 8-CTA cluster per template ----------------
struct __align__(16) Smem {
    alignas(16) float KT[MM * KSTR];   // kernel/cost, column-major (25.6KB)
    alignas(16) float U[KSTR];         // row scaling u (pad zeroed)
    float M[RPC * SR];
    float T[RPC * SR];
    float ATC[RPC * SR];
    float AdT[RPC * SR];
    float DegN[RPC];
    alignas(16) float F2[MM * FF];
    float C2[MM * MM];
    float q[MM], qC2[MM], cc[MM], fsq[MM];
    float V[MM];
    alignas(16) float Pub[2][16];      // double-buffered cluster exchange
    float Wred[NWARP][16];             // block-reduction scratch
    float Scal[4];                     // [0]=reg [1]=cmin [2]=gamma
};

__global__ void __launch_bounds__(TPB, 1) __cluster_dims__(NC, 1, 1)
k_main(const float* __restrict__ x,
       const float* __restrict__ tA,
       const float* __restrict__ tF,
       const float* __restrict__ q0,
       const float* __restrict__ a0,
       float* __restrict__ out)
{
    extern __shared__ char smem_raw[];
    Smem* s = reinterpret_cast<Smem*>(smem_raw);
    cg::cluster_group cluster = cg::this_cluster();
    const int rank = (int)cluster.block_rank();
    const int tpl  = blockIdx.x / NC;
    const int tid  = threadIdx.x;
    const int wid  = tid >> 5, lane = tid & 31;
    const int r0   = rank * RPC;
    const float P  = 1.0f / (float)NN;
    const float alpha = 1.0f / (1.0f + expf(-a0[0]));
    const float oma = 1.0f - alpha, ta = 2.0f * alpha;
    int par = 0;

    // remote Pub base pointers (loop-invariant)
    const float* rPub[NC];
    #pragma unroll
    for (int r = 0; r < NC; r++)
        rPub[r] = (const float*)cluster.map_shared_rank(&s->Pub[0][0], r);

    // ---- phase 0: per-template small data + pad init ----
    for (int i = tid; i < MM * FF; i += TPB) s->F2[i] = tF[(size_t)tpl * MM * FF + i];
    if (tid < MM * MM) s->C2[tid] = tA[tpl * MM * MM + tid];
    if (tid < KSTR - RPC) s->U[RPC + tid] = 0.f;             // U pad = 0 (never rewritten)
    if (tid >= 64 && tid < 64 + MM * (KSTR - RPC)) {          // KT pad finite
        int idx = tid - 64;
        int j = idx / (KSTR - RPC), c = RPC + idx % (KSTR - RPC);
        s->KT[j * KSTR + c] = 0.f;
    }
    if (tid == 0) {
        float qq[MM], mx = -1e30f;
        #pragma unroll
        for (int k = 0; k < MM; k++) { qq[k] = q0[tpl * MM + k]; mx = fmaxf(mx, qq[k]); }
        float ssum = 0.f;
        #pragma unroll
        for (int k = 0; k < MM; k++) { qq[k] = expf(qq[k] - mx); ssum += qq[k]; }
        #pragma unroll
        for (int k = 0; k < MM; k++) s->q[k] = qq[k] / ssum;
    }
    __syncthreads();
    if (tid < MM) {
        int j = tid;
        float a1 = 0.f, a2 = 0.f, a3 = 0.f;
        #pragma unroll
        for (int k = 0; k < MM; k++) {
            a1 += s->q[k] * s->C2[k * MM + j];
            float cj = s->C2[j * MM + k];
            a2 += cj * cj * s->q[k];
        }
        for (int c = 0; c < FF; c++) { float fv = s->F2[j * FF + c]; a3 += fv * fv; }
        s->qC2[j] = a1; s->cc[j] = a2; s->fsq[j] = a3;
    }
    __syncthreads();

    // ---- phase 1: M (feature cost), DegN, T0 = p q^T, ATC0 (closed form) ----
    for (int r = wid; r < RPC; r += NWARP) {
        int gi = r0 + r;
        const float* xr = x + (size_t)gi * FF;
        float acc[MM];
        #pragma unroll
        for (int j = 0; j < MM; j++) acc[j] = 0.f;
        float xs = 0.f;
        #pragma unroll
        for (int c = 0; c < FF / 32; c++) {
            float xv = xr[c * 32 + lane];
            xs += xv * xv;
            #pragma unroll
            for (int j = 0; j < MM; j++) acc[j] += xv * s->F2[j * FF + c * 32 + lane];
        }
        #pragma unroll
        for (int o = 16; o; o >>= 1) {
            xs += __shfl_xor_sync(0xffffffffu, xs, o);
            #pragma unroll
            for (int j = 0; j < MM; j++) acc[j] += __shfl_xor_sync(0xffffffffu, acc[j], o);
        }
        float dn = (float)(g_rowptr[gi + 1] - g_rowptr[gi]) * P;
        if (lane == 0) s->DegN[r] = dn;
        if (lane < MM) {
            int j = lane;
            s->M[r * SR + j]   = xs + s->fsq[j] - 2.f * acc[j];
            s->T[r * SR + j]   = P * s->q[j];
            s->ATC[r * SR + j] = dn * s->qC2[j];
        }
    }
    __syncthreads();

    // ---- Frank-Wolfe loop ----
    for (int fw = 0; fw < NFW; fw++) {
        // (a) G = (1-a)M + 2a(constC - 2 ATC) -> KT; stats sum|G|, min G
        float psum = 0.f, pmin = 1e30f;
        for (int li = tid; li < RPC; li += TPB) {
            float dn = s->DegN[li];
            #pragma unroll
            for (int j = 0; j < MM; j++) {
                float g = oma * s->M[li * SR + j] + ta * (dn + s->cc[j] - 2.f * s->ATC[li * SR + j]);
                s->KT[j * KSTR + li] = g;
                psum += fabsf(g);
                pmin = fminf(pmin, g);
            }
        }
        #pragma unroll
        for (int o = 16; o; o >>= 1) {
            psum += __shfl_xor_sync(0xffffffffu, psum, o);
            pmin = fminf(pmin, __shfl_xor_sync(0xffffffffu, pmin, o));
        }
        if (lane == 0) { s->Wred[wid][0] = psum; s->Wred[wid][1] = pmin; }
        __syncthreads();
        if (wid == 0) {   // parallel cross-warp reduce (lane-per-warp)
            float a = (lane < NWARP) ? s->Wred[lane][0] : 0.f;
            float b = (lane < NWARP) ? s->Wred[lane][1] : 1e30f;
            #pragma unroll
            for (int o = 16; o; o >>= 1) {
                a += __shfl_xor_sync(0xffffffffu, a, o);
                b = fminf(b, __shfl_xor_sync(0xffffffffu, b, o));
            }
            if (lane == 0) { s->Pub[par][0] = a; s->Pub[par][1] = b; }
        }
        cluster.sync();
        if (tid == 0) {   // parallel 8-rank reads
            int o = par * 16;
            float s0 = rPub[0][o], s1 = rPub[1][o], s2 = rPub[2][o], s3 = rPub[3][o],
                  s4 = rPub[4][o], s5 = rPub[5][o], s6 = rPub[6][o], s7 = rPub[7][o];
            float m0 = rPub[0][o+1], m1 = rPub[1][o+1], m2 = rPub[2][o+1], m3 = rPub[3][o+1],
                  m4 = rPub[4][o+1], m5 = rPub[5][o+1], m6 = rPub[6][o+1], m7 = rPub[7][o+1];
            float bs = ((s0+s1)+(s2+s3)) + ((s4+s5)+(s6+s7));
            float bm = fminf(fminf(fminf(m0,m1),fminf(m2,m3)), fminf(fminf(m4,m5),fminf(m6,m7)));
            s->Scal[0] = 0.05f * (bs / (float)(NN * MM)) + 1e-9f;  // reg
            s->Scal[1] = bm;                                        // cmin
        }
        if (tid < MM) s->V[tid] = 1.f;   // reset Sinkhorn scaling (g=0)
        par ^= 1;
        __syncthreads();

        // (b) K = exp(-(G - cmin)/reg), vectorized over full KT incl. pad
        {
            float inv = 1.0f / s->Scal[0], cmin = s->Scal[1];
            float4* kt4 = reinterpret_cast<float4*>(s->KT);
            for (int i = tid; i < MM * KSTR / 4; i += TPB) {
                float4 v = kt4[i];
                v.x = __expf(fminf(fmaxf((cmin - v.x) * inv, -80.f), 0.f));
                v.y = __expf(fminf(fmaxf((cmin - v.y) * inv, -80.f), 0.f));
                v.z = __expf(fminf(fmaxf((cmin - v.z) * inv, -80.f), 0.f));
                v.w = __expf(fminf(fmaxf((cmin - v.w) * inv, -80.f), 0.f));
                kt4[i] = v;
            }
        }
        __syncthreads();

        // (c) Sinkhorn: u = p/(Kv); colsum_j = (K^T u)_j; v = q/colsum
        for (int it = 0; it < NSINK; it++) {
            float vr[MM];
            #pragma unroll
            for (int j = 0; j < MM; j++) vr[j] = s->V[j];
            // phase 1: row dots -> U  (no shuffles)
            for (int li = tid; li < RPC; li += TPB) {
                float kv = 0.f;
                #pragma unroll
                for (int j = 0; j < MM; j++) kv += s->KT[j * KSTR + li] * vr[j];
                s->U[li] = __fdividef(P, kv);
            }
            __syncthreads();
            // phase 2: warp-per-column float4 sums -> Pub
            if (wid < MM) {
                const float4* kc = reinterpret_cast<const float4*>(&s->KT[wid * KSTR]);
                const float4* uc = reinterpret_cast<const float4*>(s->U);
                float c = 0.f;
                #pragma unroll
                for (int ch = 0; ch < KSTR / 128; ch++) {   // 5 chunks
                    float4 k4 = kc[ch * 32 + lane];
                    float4 u4 = uc[ch * 32 + lane];
                    c += k4.x * u4.x + k4.y * u4.y + k4.z * u4.z + k4.w * u4.w;
                }
                #pragma unroll
                for (int o = 16; o; o >>= 1) c += __shfl_xor_sync(0xffffffffu, c, o);
                if (lane == 0) s->Pub[par][wid] = c;
            }
            cluster.sync();
            if (tid < MM) {   // parallel 8-rank reads
                int o = par * 16 + tid;
                float t0 = rPub[0][o], t1 = rPub[1][o], t2 = rPub[2][o], t3 = rPub[3][o],
                      t4 = rPub[4][o], t5 = rPub[5][o], t6 = rPub[6][o], t7 = rPub[7][o];
                float tot = ((t0+t1)+(t2+t3)) + ((t4+t5)+(t6+t7));
                s->V[tid] = __fdividef(s->q[tid], tot);
            }
            par ^= 1;
            __syncthreads();
        }

        // (d) dT = u.K.v - T; Y = dT@C2 -> global; partial dots for b
        float pM = 0.f, pC = 0.f, pA = 0.f;
        {
            float vr[MM];
            #pragma unroll
            for (int j = 0; j < MM; j++) vr[j] = s->V[j];
            for (int li = tid; li < RPC; li += TPB) {
                float u = s->U[li];
                float d[MM];
                #pragma unroll
                for (int j = 0; j < MM; j++)
                    d[j] = u * s->KT[j * KSTR + li] * vr[j] - s->T[li * SR + j];
                float dn = s->DegN[li];
                #pragma unroll
                for (int j = 0; j < MM; j++) {
                    pM += s->M[li * SR + j] * d[j];
                    pC += (dn + s->cc[j]) * d[j];
                    pA += s->ATC[li * SR + j] * d[j];
                }
                float* yp = g_Y + ((size_t)tpl * NN + (r0 + li)) * MM;
                #pragma unroll
                for (int jj = 0; jj < MM; jj++) {
                    float y = 0.f;
                    #pragma unroll
                    for (int j = 0; j < MM; j++) y += d[j] * s->C2[j * MM + jj];
                    yp[jj] = y;
                }
            }
        }
        __threadfence();
        cluster.sync();

        // (e) SpMM: AdTC = A @ Y (CSR, deduped, sorted -> deterministic); pa
        float pa = 0.f;
        {
            float vr[MM];
            #pragma unroll
            for (int j = 0; j < MM; j++) vr[j] = s->V[j];
            for (int li = tid; li < RPC; li += TPB) {
                int gi = r0 + li;
                int b = g_rowptr[gi], en = g_rowptr[gi + 1];
                float acc[MM];
                #pragma unroll
                for (int j = 0; j < MM; j++) acc[j] = 0.f;
                for (int p2 = b; p2 < en; p2++) {
                    int col = g_cols[p2];
                    const float2* yp = reinterpret_cast<const float2*>(
                        g_Y + ((size_t)tpl * NN + col) * MM);
                    float2 v0 = __ldg(yp + 0), v1 = __ldg(yp + 1), v2 = __ldg(yp + 2),
                           v3 = __ldg(yp + 3), v4 = __ldg(yp + 4);
                    acc[0] += v0.x; acc[1] += v0.y;
                    acc[2] += v1.x; acc[3] += v1.y;
                    acc[4] += v2.x; acc[5] += v2.y;
                    acc[6] += v3.x; acc[7] += v3.y;
                    acc[8] += v4.x; acc[9] += v4.y;
                }
                float u = s->U[li];
                #pragma unroll
                for (int j = 0; j < MM; j++) {
                    s->AdT[li * SR + j] = acc[j];
                    float d = u * s->KT[j * KSTR + li] * vr[j] - s->T[li * SR + j];
                    pa += acc[j] * d;
                }
            }
        }

        // (f) reduce (pa, pM, pC, pA) block+cluster; compute gamma
        #pragma unroll
        for (int o = 16; o; o >>= 1) {
            pa += __shfl_xor_sync(0xffffffffu, pa, o);
            pM += __shfl_xor_sync(0xffffffffu, pM, o);
            pC += __shfl_xor_sync(0xffffffffu, pC, o);
            pA += __shfl_xor_sync(0xffffffffu, pA, o);
        }
        if (lane == 0) {
            s->Wred[wid][0] = pa; s->Wred[wid][1] = pM;
            s->Wred[wid][2] = pC; s->Wred[wid][3] = pA;
        }
        __syncthreads();
        if (wid == 0) {   // parallel cross-warp reduce
            float t0 = (lane < NWARP) ? s->Wred[lane][0] : 0.f;
            float t1 = (lane < NWARP) ? s->Wred[lane][1] : 0.f;
            float t2 = (lane < NWARP) ? s->Wred[lane][2] : 0.f;
            float t3 = (lane < NWARP) ? s->Wred[lane][3] : 0.f;
            #pragma unroll
            for (int o = 16; o; o >>= 1) {
                t0 += __shfl_xor_sync(0xffffffffu, t0, o);
                t1 += __shfl_xor_sync(0xffffffffu, t1, o);
                t2 += __shfl_xor_sync(0xffffffffu, t2, o);
                t3 += __shfl_xor_sync(0xffffffffu, t3, o);
            }
            if (lane == 0) {
                s->Pub[par][0] = t0; s->Pub[par][1] = t1;
                s->Pub[par][2] = t2; s->Pub[par][3] = t3;
            }
        }
        cluster.sync();
        if (tid == 0) {
            int o = par * 16;
            float Ta = 0.f, Tm = 0.f, Tc = 0.f, TA = 0.f;
            #pragma unroll
            for (int r = 0; r < NC; r++) {
                const float* rp = rPub[r] + o;
                Ta += rp[0]; Tm += rp[1]; Tc += rp[2]; TA += rp[3];
            }
            float a = -2.f * alpha * Ta;
            float b = oma * Tm + alpha * (Tc - 4.f * TA);
            float gam;
            if (a > 0.f) {
                gam = -b / (2.f * a + 1e-16f);
                gam = fminf(fmaxf(gam, 0.f), 1.f);
            } else {
                gam = (a + b < 0.f) ? 1.f : 0.f;
            }
            s->Scal[2] = gam;
        }
        par ^= 1;
        __syncthreads();

        // (g) T += gam*dT; ATC += gam*AdTC
        {
            float gam = s->Scal[2];
            float vr[MM];
            #pragma unroll
            for (int j = 0; j < MM; j++) vr[j] = s->V[j];
            for (int li = tid; li < RPC; li += TPB) {
                float u = s->U[li];
                #pragma unroll
                for (int j = 0; j < MM; j++) {
                    float d = u * s->KT[j * KSTR + li] * vr[j] - s->T[li * SR + j];
                    s->T[li * SR + j]   += gam * d;
                    s->ATC[li * SR + j] += gam * s->AdT[li * SR + j];
                }
            }
        }
        __syncthreads();
    }

    // ---- final FGW distance ----
    float pd = 0.f;
    for (int li = tid; li < RPC; li += TPB) {
        float dn = s->DegN[li];
        #pragma unroll
        for (int j = 0; j < MM; j++) {
            int e = li * SR + j;
            float t = s->T[e];
            pd += oma * s->M[e] * t + alpha * ((dn + s->cc[j]) * t - 2.f * s->ATC[e] * t);
        }
    }
    #pragma unroll
    for (int o = 16; o; o >>= 1) pd += __shfl_xor_sync(0xffffffffu, pd, o);
    if (lane == 0) s->Wred[wid][0] = pd;
    __syncthreads();
    if (wid == 0) {
        float a = (lane < NWARP) ? s->Wred[lane][0] : 0.f;
        #pragma unroll
        for (int o = 16; o; o >>= 1) a += __shfl_xor_sync(0xffffffffu, a, o);
        if (lane == 0) s->Pub[par][0] = a;
    }
    cluster.sync();
    if (rank == 0 && tid == 0) {
        int o = par * 16;
        float t0 = rPub[0][o], t1 = rPub[1][o], t2 = rPub[2][o], t3 = rPub[3][o],
              t4 = rPub[4][o], t5 = rPub[5][o], t6 = rPub[6][o], t7 = rPub[7][o];
        out[tpl] = ((t0+t1)+(t2+t3)) + ((t4+t5)+(t6+t7));
    }
    cluster.sync();  // keep all CTAs alive until DSMEM reads complete
}

// ---------------- launch ----------------
extern "C" void kernel_launch(void* const* d_in, const int* in_sizes, int n_in,
                              void* d_out, int out_size)
{
    const float* x  = (const float*)d_in[0];
    const int*   ei = (const int*)  d_in[1];
    const float* tA = (const float*)d_in[2];
    const float* tF = (const float*)d_in[3];
    const float* q0 = (const float*)d_in[4];
    const float* a0 = (const float*)d_in[5];
    float* out = (float*)d_out;
    int E = in_sizes[1] / 2;

    cudaFuncSetAttribute(k_main, cudaFuncAttributeMaxDynamicSharedMemorySize,
                         (int)sizeof(Smem));

    k_mark<<<(E + 255) / 256, 256>>>(ei, E);                         // 1
    k_degscan<<<(NN * 32 + 511) / 512, 512>>>();                     // 2 (grid-wide + last-block scan)
    k_fill<<<(NN * 32 + 255) / 256, 256>>>();                        // 3
    k_main<<<NT * NC, TPB, sizeof(Smem)>>>(x, tA, tF, q0, a0, out);  // 4 -> profiled
}

// round 11
// speedup vs baseline: 1.2273x; 1.0746x over previous
#include <cuda_runtime.h>
#include <cooperative_groups.h>

namespace cg = cooperative_groups;

// Problem constants (fixed shapes)
#define NN    5000      // graph nodes
#define MM    10        // template nodes
#define SR    11        // smem row stride for row-major arrays (gcd(11,32)=1)
#define KSTR  640       // KT column-major stride (pad 625 -> 640, float4-able)
#define NT    16        // templates
#define FF    128       // features
#define NFW   3         // Frank-Wolfe iters
#define NSINK 10        // Sinkhorn iters
#define NC    8         // CTAs per cluster (per template)
#define RPC   (NN/NC)   // rows per CTA = 625
#define TPB   1024      // <<< was 512: raise occupancy 25% -> 50%
#define NWARP (TPB/32)
#define WS    160       // bitmap words per row (157 used, padded)
#define EMAX  80000

// ---------------- device scratch (static; no allocation) ----------------
__device__ unsigned int g_bitmap[NN * WS];       // zero-init; k_fill leaves it clean
__device__ int   g_deg[NN];
__device__ int   g_rowptr[NN + 1];
__device__ int   g_cols[EMAX];
__device__ int   g_ctr;                          // k_degscan last-block counter (self-resetting)
__device__ float g_Y[(size_t)NT * NN * MM];      // dT@C2 per template

// ---------------- preprocessing kernels ----------------
__global__ void k_mark(const int* __restrict__ ei, int E) {
    int e = blockIdx.x * blockDim.x + threadIdx.x;
    if (e >= E) return;
    int s = ei[e];
    int d = ei[E + e];
    atomicOr(&g_bitmap[s * WS + (d >> 5)], 1u << (d & 31));
}

// Grid-wide dedup degree (warp-per-row) + last-block exclusive scan -> g_rowptr.
__global__ void k_degscan() {
    __shared__ int isLast;
    __shared__ int wsum[16];
    int gw   = (blockIdx.x * blockDim.x + threadIdx.x) >> 5;
    int lane = threadIdx.x & 31;
    if (gw < NN) {
        const unsigned int* bp = g_bitmap + (size_t)gw * WS;
        int c = 0;
        #pragma unroll
        for (int k = 0; k < 5; k++) c += __popc(bp[lane + 32 * k]);
        #pragma unroll
        for (int o = 16; o; o >>= 1) c += __shfl_xor_sync(0xffffffffu, c, o);
        if (lane == 0) g_deg[gw] = c;
    }
    __syncthreads();
    __threadfence();
    if (threadIdx.x == 0) isLast = (atomicAdd(&g_ctr, 1) == (int)gridDim.x - 1);
    __syncthreads();
    if (!isLast) return;

    // exclusive scan of g_deg[5000] with 512 threads, 10 elems each
    int tid = threadIdx.x, w = tid >> 5;
    int base = tid * 10, loc[10], ssum = 0;
    #pragma unroll
    for (int k = 0; k < 10; k++) {
        int v = (base + k < NN) ? g_deg[base + k] : 0;
        loc[k] = v; ssum += v;
    }
    int inc = ssum;
    #pragma unroll
    for (int o = 1; o < 32; o <<= 1) {
        int v = __shfl_up_sync(0xffffffffu, inc, o);
        if (lane >= o) inc += v;
    }
    if (lane == 31) wsum[w] = inc;
    __syncthreads();
    if (w == 0) {
        int v2 = (lane < 16) ? wsum[lane] : 0, i2 = v2;
        #pragma unroll
        for (int o = 1; o < 32; o <<= 1) {
            int t = __shfl_up_sync(0xffffffffu, i2, o);
            if (lane >= o) i2 += t;
        }
        if (lane < 16) wsum[lane] = i2 - v2;   // exclusive warp offsets
    }
    __syncthreads();
    int excl = wsum[w] + inc - ssum;
    #pragma unroll
    for (int k = 0; k < 10; k++) {
        if (base + k < NN) { g_rowptr[base + k] = excl; excl += loc[k]; }
    }
    if (tid == 511) g_rowptr[NN] = excl;   // all its loc are 0 -> excl = total
    if (tid == 0)   g_ctr = 0;             // reset for next call (determinism)
}

// one warp per row: emit sorted column indices (deterministic CSR) AND clear bitmap
__global__ void k_fill() {
    int w    = (blockIdx.x * blockDim.x + threadIdx.x) >> 5;
    int lane = threadIdx.x & 31;
    if (w >= NN) return;
    unsigned int* bp = g_bitmap + (size_t)w * WS;
    unsigned int wd[5];
    int c = 0;
    #pragma unroll
    for (int k = 0; k < 5; k++) {
        wd[k] = bp[lane * 5 + k];
        bp[lane * 5 + k] = 0u;
        c += __popc(wd[k]);
    }
    int inc = c;
    #pragma unroll
    for (int o = 1; o < 32; o <<= 1) {
        int v = __shfl_up_sync(0xffffffffu, inc, o);
        if (lane >= o) inc += v;
    }
    int pos = g_rowptr[w] + inc - c;
    #pragma unroll
    for (int k = 0; k < 5; k++) {
        unsigned int x = wd[k];
        int bb = (lane * 5 + k) * 32;
        while (x) {
            int b = __ffs(x) - 1;
            g_cols[pos++] = bb + b;
            x &= x - 1;
        }
    }
}

// ---------------- main FGW kernel: one 8-CTA cluster per template ----------------
struct __align__(16) Smem {
    alignas(16) float KT[MM * KSTR];   // kernel/cost, column-major (25.6KB)
    alignas(16) float U[KSTR];         // row scaling u (pad zeroed)
    float M[RPC * SR];
    float T[RPC * SR];
    float ATC[RPC * SR];
    float AdT[RPC * SR];
    float DegN[RPC];
    alignas(16) float F2[MM * FF];
    float C2[MM * MM];
    float q[MM], qC2[MM], cc[MM], fsq[MM];
    float V[MM];
    alignas(16) float Pub[2][16];      // double-buffered cluster exchange
    float Wred[NWARP][16];             // block-reduction scratch
    float Scal[4];                     // [0]=reg [1]=cmin [2]=gamma
};

__global__ void __launch_bounds__(TPB, 1) __cluster_dims__(NC, 1, 1)
k_main(const float* __restrict__ x,
       const float* __restrict__ tA,
       const float* __restrict__ tF,
       const float* __restrict__ q0,
       const float* __restrict__ a0,
       float* __restrict__ out)
{
    extern __shared__ char smem_raw[];
    Smem* s = reinterpret_cast<Smem*>(smem_raw);
    cg::cluster_group cluster = cg::this_cluster();
    const int rank = (int)cluster.block_rank();
    const int tpl  = blockIdx.x / NC;
    const int tid  = threadIdx.x;
    const int wid  = tid >> 5, lane = tid & 31;
    const int r0   = rank * RPC;
    const float P  = 1.0f / (float)NN;
    const float alpha = 1.0f / (1.0f + expf(-a0[0]));
    const float oma = 1.0f - alpha, ta = 2.0f * alpha;
    int par = 0;

    // ---- phase 0: per-template small data + pad init ----
    for (int i = tid; i < MM * FF; i += TPB) s->F2[i] = tF[(size_t)tpl * MM * FF + i];
    if (tid < MM * MM) s->C2[tid] = tA[tpl * MM * MM + tid];
    if (tid < KSTR - RPC) s->U[RPC + tid] = 0.f;             // U pad = 0 (never rewritten)
    if (tid >= 128 && tid < 128 + MM * (KSTR - RPC)) {        // KT pad finite
        int idx = tid - 128;
        int j = idx / (KSTR - RPC), c = RPC + idx % (KSTR - RPC);
        s->KT[j * KSTR + c] = 0.f;
    }
    if (tid == 0) {
        float qq[MM], mx = -1e30f;
        #pragma unroll
        for (int k = 0; k < MM; k++) { qq[k] = q0[tpl * MM + k]; mx = fmaxf(mx, qq[k]); }
        float ssum = 0.f;
        #pragma unroll
        for (int k = 0; k < MM; k++) { qq[k] = expf(qq[k] - mx); ssum += qq[k]; }
        #pragma unroll
        for (int k = 0; k < MM; k++) s->q[k] = qq[k] / ssum;
    }
    __syncthreads();
    if (tid < MM) {
        int j = tid;
        float a1 = 0.f, a2 = 0.f, a3 = 0.f;
        #pragma unroll
        for (int k = 0; k < MM; k++) {
            a1 += s->q[k] * s->C2[k * MM + j];
            float cj = s->C2[j * MM + k];
            a2 += cj * cj * s->q[k];
        }
        for (int c = 0; c < FF; c++) { float fv = s->F2[j * FF + c]; a3 += fv * fv; }
        s->qC2[j] = a1; s->cc[j] = a2; s->fsq[j] = a3;
    }
    __syncthreads();

    // ---- phase 1: M (feature cost), DegN, T0 = p q^T, ATC0 (closed form) ----
    for (int r = wid; r < RPC; r += NWARP) {
        int gi = r0 + r;
        const float* xr = x + (size_t)gi * FF;
        float acc[MM];
        #pragma unroll
        for (int j = 0; j < MM; j++) acc[j] = 0.f;
        float xs = 0.f;
        #pragma unroll
        for (int c = 0; c < FF / 32; c++) {
            float xv = xr[c * 32 + lane];
            xs += xv * xv;
            #pragma unroll
            for (int j = 0; j < MM; j++) acc[j] += xv * s->F2[j * FF + c * 32 + lane];
        }
        #pragma unroll
        for (int o = 16; o; o >>= 1) {
            xs += __shfl_xor_sync(0xffffffffu, xs, o);
            #pragma unroll
            for (int j = 0; j < MM; j++) acc[j] += __shfl_xor_sync(0xffffffffu, acc[j], o);
        }
        float dn = (float)(g_rowptr[gi + 1] - g_rowptr[gi]) * P;
        if (lane == 0) s->DegN[r] = dn;
        if (lane < MM) {
            int j = lane;
            s->M[r * SR + j]   = xs + s->fsq[j] - 2.f * acc[j];
            s->T[r * SR + j]   = P * s->q[j];
            s->ATC[r * SR + j] = dn * s->qC2[j];
        }
    }
    __syncthreads();

    // ---- Frank-Wolfe loop ----
    for (int fw = 0; fw < NFW; fw++) {
        // (a) G = (1-a)M + 2a(constC - 2 ATC) -> KT; stats sum|G|, min G
        float psum = 0.f, pmin = 1e30f;
        for (int li = tid; li < RPC; li += TPB) {
            float dn = s->DegN[li];
            #pragma unroll
            for (int j = 0; j < MM; j++) {
                float g = oma * s->M[li * SR + j] + ta * (dn + s->cc[j] - 2.f * s->ATC[li * SR + j]);
                s->KT[j * KSTR + li] = g;
                psum += fabsf(g);
                pmin = fminf(pmin, g);
            }
        }
        #pragma unroll
        for (int o = 16; o; o >>= 1) {
            psum += __shfl_xor_sync(0xffffffffu, psum, o);
            pmin = fminf(pmin, __shfl_xor_sync(0xffffffffu, pmin, o));
        }
        if (lane == 0) { s->Wred[wid][0] = psum; s->Wred[wid][1] = pmin; }
        __syncthreads();
        if (wid == 0) {   // parallel cross-warp reduce (lane-per-warp, NWARP=32)
            float a = s->Wred[lane][0];
            float b = s->Wred[lane][1];
            #pragma unroll
            for (int o = 16; o; o >>= 1) {
                a += __shfl_xor_sync(0xffffffffu, a, o);
                b = fminf(b, __shfl_xor_sync(0xffffffffu, b, o));
            }
            if (lane == 0) { s->Pub[par][0] = a; s->Pub[par][1] = b; }
        }
        cluster.sync();
        if (tid < 2 * NC) {   // 16 threads: 8 sums + 8 mins in parallel
            int r = tid & 7;
            const float* rp = (const float*)cluster.map_shared_rank(&s->Pub[0][0], r);
            float v = rp[par * 16 + (tid >> 3)];
            // reduce within two groups of 8 lanes
            #pragma unroll
            for (int o = 4; o; o >>= 1) {
                float t = __shfl_xor_sync(0xffffu, v, o);
                v = (tid >> 3) ? fminf(v, t) : (v + t);
            }
            if (tid == 0) s->Scal[0] = 0.05f * (v / (float)(NN * MM)) + 1e-9f;  // reg
            if (tid == 8) s->Scal[1] = v;                                        // cmin
        }
        if (tid >= 32 && tid < 32 + MM) s->V[tid - 32] = 1.f;   // reset Sinkhorn scaling
        par ^= 1;
        __syncthreads();

        // (b) K = exp(-(G - cmin)/reg), vectorized over full KT incl. pad
        {
            float inv = 1.0f / s->Scal[0], cmin = s->Scal[1];
            float4* kt4 = reinterpret_cast<float4*>(s->KT);
            for (int i = tid; i < MM * KSTR / 4; i += TPB) {
                float4 v = kt4[i];
                v.x = __expf(fminf(fmaxf((cmin - v.x) * inv, -80.f), 0.f));
                v.y = __expf(fminf(fmaxf((cmin - v.y) * inv, -80.f), 0.f));
                v.z = __expf(fminf(fmaxf((cmin - v.z) * inv, -80.f), 0.f));
                v.w = __expf(fminf(fmaxf((cmin - v.w) * inv, -80.f), 0.f));
                kt4[i] = v;
            }
        }
        __syncthreads();

        // (c) Sinkhorn: u = p/(Kv); colsum_j = (K^T u)_j; v = q/colsum
        for (int it = 0; it < NSINK; it++) {
            float vr[MM];
            #pragma unroll
            for (int j = 0; j < MM; j++) vr[j] = s->V[j];
            // phase 1: row dots -> U  (no shuffles; 1 row/thread)
            for (int li = tid; li < RPC; li += TPB) {
                float kv = 0.f;
                #pragma unroll
                for (int j = 0; j < MM; j++) kv += s->KT[j * KSTR + li] * vr[j];
                s->U[li] = __fdividef(P, kv);
            }
            __syncthreads();
            // phase 2: warp-per-column float4 sums -> Pub
            if (wid < MM) {
                const float4* kc = reinterpret_cast<const float4*>(&s->KT[wid * KSTR]);
                const float4* uc = reinterpret_cast<const float4*>(s->U);
                float c = 0.f;
                #pragma unroll
                for (int ch = 0; ch < KSTR / 128; ch++) {   // 5 chunks
                    float4 k4 = kc[ch * 32 + lane];
                    float4 u4 = uc[ch * 32 + lane];
                    c += k4.x * u4.x + k4.y * u4.y + k4.z * u4.z + k4.w * u4.w;
                }
                #pragma unroll
                for (int o = 16; o; o >>= 1) c += __shfl_xor_sync(0xffffffffu, c, o);
                if (lane == 0) s->Pub[par][wid] = c;
            }
            cluster.sync();
            if (tid < MM) {   // parallel 8-rank reads (pointers rematerialized)
                int o = par * 16 + tid;
                float tot = 0.f;
                #pragma unroll
                for (int r = 0; r < NC; r++) {
                    const float* rp = (const float*)cluster.map_shared_rank(&s->Pub[0][0], r);
                    tot += rp[o];
                }
                s->V[tid] = __fdividef(s->q[tid], tot);
            }
            par ^= 1;
            __syncthreads();
        }

        // (d) dT = u.K.v - T; Y = dT@C2 -> global; partial dots for b
        float pM = 0.f, pC = 0.f, pA = 0.f;
        {
            float vr[MM];
            #pragma unroll
            for (int j = 0; j < MM; j++) vr[j] = s->V[j];
            for (int li = tid; li < RPC; li += TPB) {
                float u = s->U[li];
                float d[MM];
                #pragma unroll
                for (int j = 0; j < MM; j++)
                    d[j] = u * s->KT[j * KSTR + li] * vr[j] - s->T[li * SR + j];
                float dn = s->DegN[li];
                #pragma unroll
                for (int j = 0; j < MM; j++) {
                    pM += s->M[li * SR + j] * d[j];
                    pC += (dn + s->cc[j]) * d[j];
                    pA += s->ATC[li * SR + j] * d[j];
                }
                float* yp = g_Y + ((size_t)tpl * NN + (r0 + li)) * MM;
                #pragma unroll
                for (int jj = 0; jj < MM; jj++) {
                    float y = 0.f;
                    #pragma unroll
                    for (int j = 0; j < MM; j++) y += d[j] * s->C2[j * MM + jj];
                    yp[jj] = y;
                }
            }
        }
        __threadfence();
        cluster.sync();

        // (e) SpMM: AdTC = A @ Y (CSR, deduped, sorted -> deterministic); pa
        float pa = 0.f;
        {
            float vr[MM];
            #pragma unroll
            for (int j = 0; j < MM; j++) vr[j] = s->V[j];
            for (int li = tid; li < RPC; li += TPB) {
                int gi = r0 + li;
                int b = g_rowptr[gi], en = g_rowptr[gi + 1];
                float acc[MM];
                #pragma unroll
                for (int j = 0; j < MM; j++) acc[j] = 0.f;
                for (int p2 = b; p2 < en; p2++) {
                    int col = g_cols[p2];
                    const float2* yp = reinterpret_cast<const float2*>(
                        g_Y + ((size_t)tpl * NN + col) * MM);
                    float2 v0 = __ldg(yp + 0), v1 = __ldg(yp + 1), v2 = __ldg(yp + 2),
                           v3 = __ldg(yp + 3), v4 = __ldg(yp + 4);
                    acc[0] += v0.x; acc[1] += v0.y;
                    acc[2] += v1.x; acc[3] += v1.y;
                    acc[4] += v2.x; acc[5] += v2.y;
                    acc[6] += v3.x; acc[7] += v3.y;
                    acc[8] += v4.x; acc[9] += v4.y;
                }
                float u = s->U[li];
                #pragma unroll
                for (int j = 0; j < MM; j++) {
                    s->AdT[li * SR + j] = acc[j];
                    float d = u * s->KT[j * KSTR + li] * vr[j] - s->T[li * SR + j];
                    pa += acc[j] * d;
                }
            }
        }

        // (f) reduce (pa, pM, pC, pA) block+cluster; compute gamma
        #pragma unroll
        for (int o = 16; o; o >>= 1) {
            pa += __shfl_xor_sync(0xffffffffu, pa, o);
            pM += __shfl_xor_sync(0xffffffffu, pM, o);
            pC += __shfl_xor_sync(0xffffffffu, pC, o);
            pA += __shfl_xor_sync(0xffffffffu, pA, o);
        }
        if (lane == 0) {
            s->Wred[wid][0] = pa; s->Wred[wid][1] = pM;
            s->Wred[wid][2] = pC; s->Wred[wid][3] = pA;
        }
        __syncthreads();
        if (wid == 0) {   // parallel cross-warp reduce (32 warps)
            float t0 = s->Wred[lane][0];
            float t1 = s->Wred[lane][1];
            float t2 = s->Wred[lane][2];
            float t3 = s->Wred[lane][3];
            #pragma unroll
            for (int o = 16; o; o >>= 1) {
                t0 += __shfl_xor_sync(0xffffffffu, t0, o);
                t1 += __shfl_xor_sync(0xffffffffu, t1, o);
                t2 += __shfl_xor_sync(0xffffffffu, t2, o);
                t3 += __shfl_xor_sync(0xffffffffu, t3, o);
            }
            if (lane == 0) {
                s->Pub[par][0] = t0; s->Pub[par][1] = t1;
                s->Pub[par][2] = t2; s->Pub[par][3] = t3;
            }
        }
        cluster.sync();
        if (tid == 0) {
            int o = par * 16;
            float Ta = 0.f, Tm = 0.f, Tc = 0.f, TA = 0.f;
            #pragma unroll
            for (int r = 0; r < NC; r++) {
                const float* rp = (const float*)cluster.map_shared_rank(&s->Pub[0][0], r) + o;
                Ta += rp[0]; Tm += rp[1]; Tc += rp[2]; TA += rp[3];
            }
            float a = -2.f * alpha * Ta;
            float b = oma * Tm + alpha * (Tc - 4.f * TA);
            float gam;
            if (a > 0.f) {
                gam = -b / (2.f * a + 1e-16f);
                gam = fminf(fmaxf(gam, 0.f), 1.f);
            } else {
                gam = (a + b < 0.f) ? 1.f : 0.f;
            }
            s->Scal[2] = gam;
        }
        par ^= 1;
        __syncthreads();

        // (g) T += gam*dT; ATC += gam*AdTC
        {
            float gam = s->Scal[2];
            float vr[MM];
            #pragma unroll
            for (int j = 0; j < MM; j++) vr[j] = s->V[j];
            for (int li = tid; li < RPC; li += TPB) {
                float u = s->U[li];
                #pragma unroll
                for (int j = 0; j < MM; j++) {
                    float d = u * s->KT[j * KSTR + li] * vr[j] - s->T[li * SR + j];
                    s->T[li * SR + j]   += gam * d;
                    s->ATC[li * SR + j] += gam * s->AdT[li * SR + j];
                }
            }
        }
        __syncthreads();
    }

    // ---- final FGW distance ----
    float pd = 0.f;
    for (int li = tid; li < RPC; li += TPB) {
        float dn = s->DegN[li];
        #pragma unroll
        for (int j = 0; j < MM; j++) {
            int e = li * SR + j;
            float t = s->T[e];
            pd += oma * s->M[e] * t + alpha * ((dn + s->cc[j]) * t - 2.f * s->ATC[e] * t);
        }
    }
    #pragma unroll
    for (int o = 16; o; o >>= 1) pd += __shfl_xor_sync(0xffffffffu, pd, o);
    if (lane == 0) s->Wred[wid][0] = pd;
    __syncthreads();
    if (wid == 0) {
        float a = s->Wred[lane][0];
        #pragma unroll
        for (int o = 16; o; o >>= 1) a += __shfl_xor_sync(0xffffffffu, a, o);
        if (lane == 0) s->Pub[par][0] = a;
    }
    cluster.sync();
    if (rank == 0 && tid == 0) {
        int o = par * 16;
        float tot = 0.f;
        #pragma unroll
        for (int r = 0; r < NC; r++) {
            const float* rp = (const float*)cluster.map_shared_rank(&s->Pub[0][0], r);
            tot += rp[o];
        }
        out[tpl] = tot;
    }
    cluster.sync();  // keep all CTAs alive until DSMEM reads complete
}

// ---------------- launch ----------------
extern "C" void kernel_launch(void* const* d_in, const int* in_sizes, int n_in,
                              void* d_out, int out_size)
{
    const float* x  = (const float*)d_in[0];
    const int*   ei = (const int*)  d_in[1];
    const float* tA = (const float*)d_in[2];
    const float* tF = (const float*)d_in[3];
    const float* q0 = (const float*)d_in[4];
    const float* a0 = (const float*)d_in[5];
    float* out = (float*)d_out;
    int E = in_sizes[1] / 2;

    cudaFuncSetAttribute(k_main, cudaFuncAttributeMaxDynamicSharedMemorySize,
                         (int)sizeof(Smem));

    k_mark<<<(E + 255) / 256, 256>>>(ei, E);                         // 1
    k_degscan<<<(NN * 32 + 511) / 512, 512>>>();                     // 2
    k_fill<<<(NN * 32 + 255) / 256, 256>>>();                        // 3
    k_main<<<NT * NC, TPB, sizeof(Smem)>>>(x, tA, tF, q0, a0, out);  // 4 -> profiled
}